// round 14
// baseline (speedup 1.0000x reference)
#include <cuda_runtime.h>
#include <cuda_fp16.h>
#include <cstdint>
#include <math.h>

#define N_NODES 8192
#define DMODEL 1024
#define FINT 4096
#define KTOT 3072
#define NEDGE 262144
#define NKEY (2 * N_NODES)
#define LN_EPS 1e-6f
#define NROWBLK 64
#define G1_BLOCKS 1024
#define G2_BLOCKS 256

// ---------------- PTX helpers ---------------------------------------------------
__device__ __forceinline__ uint32_t smem_u32(const void* p) {
    uint32_t a;
    asm("{ .reg .u64 t; cvta.to.shared.u64 t, %1; cvt.u32.u64 %0, t; }" : "=r"(a) : "l"(p));
    return a;
}
#define CP16(dst, src) asm volatile("cp.async.cg.shared.global [%0], [%1], 16;" :: "r"(dst), "l"(src))
#define CP_COMMIT()    asm volatile("cp.async.commit_group;" ::: "memory")
#define CP_WAIT3()     asm volatile("cp.async.wait_group 3;" ::: "memory")

__device__ __forceinline__ void ldsm4(uint32_t* r, uint32_t a) {
    asm volatile("ldmatrix.sync.aligned.m8n8.x4.shared.b16 {%0,%1,%2,%3}, [%4];"
                 : "=r"(r[0]), "=r"(r[1]), "=r"(r[2]), "=r"(r[3]) : "r"(a));
}
__device__ __forceinline__ void ldsm4t(uint32_t* r, uint32_t a) {
    asm volatile("ldmatrix.sync.aligned.m8n8.x4.trans.shared.b16 {%0,%1,%2,%3}, [%4];"
                 : "=r"(r[0]), "=r"(r[1]), "=r"(r[2]), "=r"(r[3]) : "r"(a));
}
__device__ __forceinline__ void mma16816(float* d, const uint32_t* a, const uint32_t* b) {
    asm volatile("mma.sync.aligned.m16n8k16.row.col.f32.f16.f16.f32 "
                 "{%0,%1,%2,%3}, {%4,%5,%6,%7}, {%8,%9}, {%0,%1,%2,%3};"
                 : "+f"(d[0]), "+f"(d[1]), "+f"(d[2]), "+f"(d[3])
                 : "r"(a[0]), "r"(a[1]), "r"(a[2]), "r"(a[3]), "r"(b[0]), "r"(b[1]));
}

// ---------------- scratch ----------------------------------------------------
__device__ __half g_xh[(size_t)N_NODES * DMODEL];
__device__ __half g_Ahi[(size_t)N_NODES * KTOT];
__device__ __half g_Bhi[(size_t)KTOT * FINT];
__device__ __half g_Whi[(size_t)FINT * DMODEL];
__device__ __half g_Mhi[(size_t)N_NODES * FINT];
__device__ int g_cnt[NKEY];
__device__ int g_off[NKEY];
__device__ int g_cur[NKEY];
__device__ int g_srcbuf[NEDGE];
__device__ int g_rowdone[NROWBLK];

__device__ __forceinline__ unsigned short h_rn(float x) {
    __half h = __float2half_rn(x);
    return *(unsigned short*)&h;
}

// ---------------- pipeline kernels ---------------------------------------------
__global__ void zero_cnt_kernel() {
    int i = blockIdx.x * blockDim.x + threadIdx.x;
    if (i < NKEY) g_cnt[i] = 0;
    if (i < NROWBLK) g_rowdone[i] = 0;
}

__global__ __launch_bounds__(256) void ln_kernel(const float* __restrict__ hs,
                                                 const float* __restrict__ gamma,
                                                 const float* __restrict__ beta) {
    int n = blockIdx.x;
    int t = threadIdx.x;
    const float4 v = ((const float4*)(hs + (size_t)n * DMODEL))[t];
    float s  = v.x + v.y + v.z + v.w;
    float sq = v.x * v.x + v.y * v.y + v.z * v.z + v.w * v.w;
    __shared__ float red[16];
    for (int o = 16; o > 0; o >>= 1) {
        s  += __shfl_down_sync(0xffffffff, s,  o);
        sq += __shfl_down_sync(0xffffffff, sq, o);
    }
    int wid = t >> 5, lid = t & 31;
    if (lid == 0) { red[wid] = s; red[8 + wid] = sq; }
    __syncthreads();
    if (wid == 0) {
        s  = (lid < 8) ? red[lid]     : 0.f;
        sq = (lid < 8) ? red[8 + lid] : 0.f;
        for (int o = 4; o > 0; o >>= 1) {
            s  += __shfl_down_sync(0xffffffff, s,  o);
            sq += __shfl_down_sync(0xffffffff, sq, o);
        }
        if (lid == 0) { red[0] = s; red[1] = sq; }
    }
    __syncthreads();
    float mean = red[0] * (1.f / DMODEL);
    float var  = red[1] * (1.f / DMODEL) - mean * mean;
    float rstd = rsqrtf(var + LN_EPS);
    const float4 g = ((const float4*)gamma)[t];
    const float4 b = ((const float4*)beta)[t];
    float4 o;
    o.x = (v.x - mean) * rstd * g.x + b.x;
    o.y = (v.y - mean) * rstd * g.y + b.y;
    o.z = (v.z - mean) * rstd * g.z + b.z;
    o.w = (v.w - mean) * rstd * g.w + b.w;
    ushort4 hv = { h_rn(o.x), h_rn(o.y), h_rn(o.z), h_rn(o.w) };
    ((ushort4*)g_xh)[(size_t)n * (DMODEL / 4) + t] = hv;
    size_t a = ((size_t)n * KTOT + 2048) / 4 + t;
    ((ushort4*)g_Ahi)[a] = hv;
}

__global__ void count_kernel(const int* __restrict__ ei, const int* __restrict__ et) {
    int e = blockIdx.x * blockDim.x + threadIdx.x;
    if (e < NEDGE) atomicAdd(&g_cnt[et[e] * N_NODES + ei[NEDGE + e]], 1);
}

__global__ __launch_bounds__(1024) void scan_kernel() {
    int tid = threadIdx.x;
    int lane = tid & 31, wid = tid >> 5;
    int base = tid * 16;
    int loc[16];
    int s = 0;
    #pragma unroll
    for (int i = 0; i < 16; i++) { loc[i] = s; s += g_cnt[base + i]; }
    int inc = s;
    #pragma unroll
    for (int o = 1; o < 32; o <<= 1) {
        int v = __shfl_up_sync(0xffffffff, inc, o);
        if (lane >= o) inc += v;
    }
    __shared__ int wtot[32];
    if (lane == 31) wtot[wid] = inc;
    __syncthreads();
    if (wid == 0) {
        int w = wtot[lane];
        int wi = w;
        #pragma unroll
        for (int o = 1; o < 32; o <<= 1) {
            int v = __shfl_up_sync(0xffffffff, wi, o);
            if (lane >= o) wi += v;
        }
        wtot[lane] = wi - w;
    }
    __syncthreads();
    int ex = wtot[wid] + (inc - s);
    #pragma unroll
    for (int i = 0; i < 16; i++) {
        int o = ex + loc[i];
        g_off[base + i] = o;
        g_cur[base + i] = o;
    }
}

__global__ void bucket_kernel(const int* __restrict__ ei, const int* __restrict__ et) {
    int e = blockIdx.x * blockDim.x + threadIdx.x;
    if (e < NEDGE) {
        int key = et[e] * N_NODES + ei[NEDGE + e];
        int pos = atomicAdd(&g_cur[key], 1);
        g_srcbuf[pos] = ei[e];
    }
}

__global__ __launch_bounds__(128) void gather_kernel() {
    int key = blockIdx.x;
    int node = key & (N_NODES - 1);
    int r = key >> 13;
    int off = g_off[key];
    int cnt = g_cnt[key];
    int t = threadIdx.x;

    float2 acc[4] = { {0.f,0.f}, {0.f,0.f}, {0.f,0.f}, {0.f,0.f} };
    const uint4* xrow = (const uint4*)g_xh;
    int i = 0;
    for (; i + 2 <= cnt; i += 2) {
        int s0 = g_srcbuf[off + i];
        int s1 = g_srcbuf[off + i + 1];
        uint4 v0 = xrow[(size_t)s0 * 128 + t];
        uint4 v1 = xrow[(size_t)s1 * 128 + t];
        const __half2* h0 = (const __half2*)&v0;
        const __half2* h1 = (const __half2*)&v1;
        #pragma unroll
        for (int j = 0; j < 4; j++) {
            float2 f0 = __half22float2(h0[j]);
            float2 f1 = __half22float2(h1[j]);
            acc[j].x += f0.x + f1.x;
            acc[j].y += f0.y + f1.y;
        }
    }
    if (i < cnt) {
        int s0 = g_srcbuf[off + i];
        uint4 v0 = xrow[(size_t)s0 * 128 + t];
        const __half2* h0 = (const __half2*)&v0;
        #pragma unroll
        for (int j = 0; j < 4; j++) {
            float2 f0 = __half22float2(h0[j]);
            acc[j].x += f0.x;
            acc[j].y += f0.y;
        }
    }
    float sc = 1.f / (float)max(cnt, 1);
    ushort4 o0, o1;
    o0.x = h_rn(acc[0].x * sc); o0.y = h_rn(acc[0].y * sc);
    o0.z = h_rn(acc[1].x * sc); o0.w = h_rn(acc[1].y * sc);
    o1.x = h_rn(acc[2].x * sc); o1.y = h_rn(acc[2].y * sc);
    o1.z = h_rn(acc[3].x * sc); o1.w = h_rn(acc[3].y * sc);
    size_t a = ((size_t)node * KTOT + (size_t)r * 1024 + t * 8) >> 2;
    ((ushort4*)g_Ahi)[a] = o0;
    ((ushort4*)g_Ahi)[a + 1] = o1;
}

__global__ void cvt_kernel(const float* __restrict__ src,
                           __half* __restrict__ dst, size_t n4) {
    size_t i = (size_t)blockIdx.x * blockDim.x + threadIdx.x;
    for (; i < n4; i += (size_t)gridDim.x * blockDim.x) {
        float4 v = ((const float4*)src)[i];
        ushort4 hv = { h_rn(v.x), h_rn(v.y), h_rn(v.z), h_rn(v.w) };
        ((ushort4*)dst)[i] = hv;
    }
}

// ---- fused fp16 GEMM1+GEMM2, 1280 blocks, 4-stage cp.async --------------------
#define STAGE_BYTES 49152
#define OFF_BHI 16384
#define NSTAGE 4
#define SMEM_DYN (NSTAGE * STAGE_BYTES)
#define EPIPITCH 264

__device__ __forceinline__ uint32_t a_off(int row, int q) {
    return (uint32_t)(row * 128 + ((q ^ (row & 7)) << 4));
}
__device__ __forceinline__ uint32_t b_off(int row, int q) {
    return (uint32_t)(row * 512 + (((q & 24) | ((q & 7) ^ (row & 7))) << 4));
}

__global__ __launch_bounds__(256, 1) void gemm_fused(
    const __half* __restrict__ A1, const __half* __restrict__ B1,
    const __half* __restrict__ B2,
    __half* __restrict__ mid,
    const float* __restrict__ bias, const float* __restrict__ residual,
    float* __restrict__ outF)
{
    extern __shared__ __align__(1024) char smem[];
    const uint32_t sb = smem_u32(smem);
    const int tid = threadIdx.x, wid = tid >> 5, lane = tid & 31;
    const int b = blockIdx.x;
    const bool isG1 = (b < G1_BLOCKS);

    int rowBase, nBase, K, ldA, ldB;
    const __half* A;
    const __half* B;
    if (isG1) {
        rowBase = (b >> 4) * 128;
        nBase   = (b & 15) * 256;
        K = KTOT; ldA = KTOT; ldB = FINT;
        A = A1; B = B1;
    } else {
        int j = b - G1_BLOCKS;
        rowBase = (j >> 2) * 128;
        nBase   = (j & 3) * 256;
        K = FINT; ldA = FINT; ldB = DMODEL;
        A = mid; B = B2;
        if (tid == 0) {
            while (atomicAdd(&g_rowdone[rowBase >> 7], 0) < 16) { }
        }
        __syncthreads();
        __threadfence();
    }

    const int warp_m = (wid >> 2) * 64;
    const int warp_n = (wid & 3) * 64;
    const int lr = lane & 15, lc = lane >> 4;
    const int nchunk = K >> 6;

    float acc[4][8][4];
    #pragma unroll
    for (int i = 0; i < 4; i++)
        #pragma unroll
        for (int j = 0; j < 8; j++)
            #pragma unroll
            for (int k = 0; k < 4; k++) acc[i][j][k] = 0.f;

    auto load_chunk = [&](int c, int s) {
        const uint32_t sbase = sb + s * STAGE_BYTES;
        const int kb = c * 64;
        #pragma unroll
        for (int i = 0; i < 4; i++) {
            int v = tid + i * 256;
            int row = v >> 3, q = v & 7;
            uint32_t so = sbase + a_off(row, q);
            size_t g = (size_t)(rowBase + row) * ldA + kb + q * 8;
            CP16(so, A + g);
        }
        #pragma unroll
        for (int i = 0; i < 8; i++) {
            int v = tid + i * 256;
            int row = v >> 5, q = v & 31;
            uint32_t so = sbase + OFF_BHI + b_off(row, q);
            size_t g = (size_t)(kb + row) * ldB + nBase + q * 8;
            CP16(so, B + g);
        }
    };

    load_chunk(0, 0); CP_COMMIT();
    load_chunk(1, 1); CP_COMMIT();
    load_chunk(2, 2); CP_COMMIT();
    load_chunk(3, 3); CP_COMMIT();

    for (int c = 0; c < nchunk; c++) {
        CP_WAIT3();
        __syncthreads();
        const int slot = c % NSTAGE;
        const uint32_t base = sb + slot * STAGE_BYTES;
        #pragma unroll
        for (int ks = 0; ks < 4; ks++) {
            uint32_t ah[4][4];
            #pragma unroll
            for (int mi = 0; mi < 4; mi++) {
                int row = warp_m + mi * 16 + lr;
                int q = ks * 2 + lc;
                ldsm4(ah[mi], base + a_off(row, q));
            }
            #pragma unroll
            for (int np = 0; np < 4; np++) {
                int row = ks * 16 + lr;
                int q = (warp_n >> 3) + np * 2 + lc;
                uint32_t th[4];
                ldsm4t(th, base + OFF_BHI + b_off(row, q));
                uint32_t b0[2] = { th[0], th[1] }, b1[2] = { th[2], th[3] };
                #pragma unroll
                for (int mi = 0; mi < 4; mi++) {
                    mma16816(acc[mi][np * 2], ah[mi], b0);
                    mma16816(acc[mi][np * 2 + 1], ah[mi], b1);
                }
            }
        }
        __syncthreads();
        if (c + NSTAGE < nchunk) load_chunk(c + NSTAGE, slot);
        CP_COMMIT();
    }

    if (isG1) {
        unsigned short* stH = (unsigned short*)smem;
        #pragma unroll
        for (int mi = 0; mi < 4; mi++) {
            #pragma unroll
            for (int ni = 0; ni < 8; ni++) {
                int rl0 = warp_m + mi * 16 + (lane >> 2);
                int cl  = warp_n + ni * 8 + (lane & 3) * 2;
                #pragma unroll
                for (int h = 0; h < 2; h++) {
                    int rl = rl0 + h * 8;
                    float x0 = acc[mi][ni][h * 2 + 0];
                    float x1 = acc[mi][ni][h * 2 + 1];
                    int gc = nBase + cl;
                    x0 = fmaxf(x0 + bias[gc], 0.f);
                    x1 = fmaxf(x1 + bias[gc + 1], 0.f);
                    ushort2 hv = { h_rn(x0), h_rn(x1) };
                    *(ushort2*)&stH[rl * EPIPITCH + cl] = hv;
                }
            }
        }
        __syncthreads();
        #pragma unroll
        for (int i = 0; i < 16; i++) {
            int idx = tid + i * 256;
            int row = idx >> 5, ch = idx & 31;
            uint4 vh = *(uint4*)&stH[row * EPIPITCH + ch * 8];
            size_t go = (size_t)(rowBase + row) * ldB + nBase + ch * 8;
            *(uint4*)&mid[go] = vh;
        }
        __threadfence();
        __syncthreads();
        if (tid == 0) atomicAdd(&g_rowdone[rowBase >> 7], 1);
    } else {
        #pragma unroll
        for (int mi = 0; mi < 4; mi++) {
            #pragma unroll
            for (int ni = 0; ni < 8; ni++) {
                int r0 = rowBase + warp_m + mi * 16 + (lane >> 2);
                int col = nBase + warp_n + ni * 8 + (lane & 3) * 2;
                #pragma unroll
                for (int h = 0; h < 2; h++) {
                    int row = r0 + h * 8;
                    float x0 = acc[mi][ni][h * 2 + 0];
                    float x1 = acc[mi][ni][h * 2 + 1];
                    size_t go = (size_t)row * ldB + col;
                    float2 res = *(const float2*)&residual[go];
                    float2 y = { x0 + res.x, x1 + res.y };
                    *(float2*)&outF[go] = y;
                }
            }
        }
    }
}

// ---------------- launch -------------------------------------------------------
extern "C" void kernel_launch(void* const* d_in, const int* in_sizes, int n_in,
                              void* d_out, int out_size) {
    const float* hidden = (const float*)d_in[0];
    const float* weight = (const float*)d_in[1];
    const float* root   = (const float*)d_in[2];
    const float* bias   = (const float*)d_in[3];
    const float* wo     = (const float*)d_in[4];
    const float* gamma  = (const float*)d_in[5];
    const float* beta   = (const float*)d_in[6];
    const int*   ei     = (const int*)d_in[7];
    const int*   et     = (const int*)d_in[8];
    float* out = (float*)d_out;

    __half *gAhi, *gBhi, *gWhi, *gMhi;
    cudaGetSymbolAddress((void**)&gAhi, g_Ahi);
    cudaGetSymbolAddress((void**)&gBhi, g_Bhi);
    cudaGetSymbolAddress((void**)&gWhi, g_Whi);
    cudaGetSymbolAddress((void**)&gMhi, g_Mhi);

    cudaFuncSetAttribute(gemm_fused, cudaFuncAttributeMaxDynamicSharedMemorySize, SMEM_DYN);

    static cudaStream_t sA = nullptr;
    static cudaEvent_t evFork = nullptr, evA = nullptr;
    if (!sA) {
        cudaStreamCreateWithFlags(&sA, cudaStreamNonBlocking);
        cudaEventCreateWithFlags(&evFork, cudaEventDisableTiming);
        cudaEventCreateWithFlags(&evA,    cudaEventDisableTiming);
    }

    cudaEventRecord(evFork, 0);
    cudaStreamWaitEvent(sA, evFork, 0);

    // stream A: zero -> count -> scan -> bucket
    zero_cnt_kernel<<<NKEY / 256, 256, 0, sA>>>();
    count_kernel<<<NEDGE / 256, 256, 0, sA>>>(ei, et);
    scan_kernel<<<1, 1024, 0, sA>>>();
    bucket_kernel<<<NEDGE / 256, 256, 0, sA>>>(ei, et);
    cudaEventRecord(evA, sA);

    // stream 0: ln + weight converts (overlap sA chain)
    ln_kernel<<<N_NODES, 256>>>(hidden, gamma, beta);
    cvt_kernel<<<2048, 256>>>(weight, gBhi, (size_t)2048 * FINT / 4);
    cvt_kernel<<<1024, 256>>>(root, gBhi + (size_t)2048 * FINT, (size_t)1024 * FINT / 4);
    cvt_kernel<<<1024, 256>>>(wo, gWhi, (size_t)FINT * DMODEL / 4);

    // join: gather needs bucket (sA) + ln (s0)
    cudaStreamWaitEvent(0, evA, 0);
    gather_kernel<<<NKEY, 128>>>();

    // fused GEMM1 + GEMM2 (flag-based row dependency, stream-ordered after gather)
    gemm_fused<<<G1_BLOCKS + G2_BLOCKS, 256, SMEM_DYN>>>(
        gAhi, gBhi, gWhi, gMhi, bias, hidden, out);
}

// round 15
// speedup vs baseline: 1.0263x; 1.0263x over previous
#include <cuda_runtime.h>
#include <cuda_fp16.h>
#include <cstdint>
#include <math.h>

#define N_NODES 8192
#define DMODEL 1024
#define FINT 4096
#define KTOT 3072
#define NEDGE 262144
#define NKEY (2 * N_NODES)
#define LN_EPS 1e-6f
#define NROWBLK 64
#define G1_BLOCKS 1024
#define G2_BLOCKS 256

// ---------------- PTX helpers ---------------------------------------------------
__device__ __forceinline__ uint32_t smem_u32(const void* p) {
    uint32_t a;
    asm("{ .reg .u64 t; cvta.to.shared.u64 t, %1; cvt.u32.u64 %0, t; }" : "=r"(a) : "l"(p));
    return a;
}
#define CP16(dst, src) asm volatile("cp.async.cg.shared.global [%0], [%1], 16;" :: "r"(dst), "l"(src))
#define CP_COMMIT()    asm volatile("cp.async.commit_group;" ::: "memory")
#define CP_WAIT2()     asm volatile("cp.async.wait_group 2;" ::: "memory")

__device__ __forceinline__ void ldsm4(uint32_t* r, uint32_t a) {
    asm volatile("ldmatrix.sync.aligned.m8n8.x4.shared.b16 {%0,%1,%2,%3}, [%4];"
                 : "=r"(r[0]), "=r"(r[1]), "=r"(r[2]), "=r"(r[3]) : "r"(a));
}
__device__ __forceinline__ void ldsm4t(uint32_t* r, uint32_t a) {
    asm volatile("ldmatrix.sync.aligned.m8n8.x4.trans.shared.b16 {%0,%1,%2,%3}, [%4];"
                 : "=r"(r[0]), "=r"(r[1]), "=r"(r[2]), "=r"(r[3]) : "r"(a));
}
__device__ __forceinline__ void mma16816(float* d, const uint32_t* a, const uint32_t* b) {
    asm volatile("mma.sync.aligned.m16n8k16.row.col.f32.f16.f16.f32 "
                 "{%0,%1,%2,%3}, {%4,%5,%6,%7}, {%8,%9}, {%0,%1,%2,%3};"
                 : "+f"(d[0]), "+f"(d[1]), "+f"(d[2]), "+f"(d[3])
                 : "r"(a[0]), "r"(a[1]), "r"(a[2]), "r"(a[3]), "r"(b[0]), "r"(b[1]));
}

// ---------------- scratch ----------------------------------------------------
__device__ __half g_xh[(size_t)N_NODES * DMODEL];
__device__ __half g_Ahi[(size_t)N_NODES * KTOT];
__device__ __half g_Bhi[(size_t)KTOT * FINT];
__device__ __half g_Whi[(size_t)FINT * DMODEL];
__device__ __half g_Mhi[(size_t)N_NODES * FINT];
__device__ int g_cnt[NKEY];
__device__ int g_off[NKEY];
__device__ int g_cur[NKEY];
__device__ int g_srcbuf[NEDGE];
__device__ int g_rowdone[NROWBLK];

__device__ __forceinline__ unsigned short h_rn(float x) {
    __half h = __float2half_rn(x);
    return *(unsigned short*)&h;
}

// ---------------- pipeline kernels ---------------------------------------------
__global__ void zero_cnt_kernel() {
    int i = blockIdx.x * blockDim.x + threadIdx.x;
    if (i < NKEY) g_cnt[i] = 0;
    if (i < NROWBLK) g_rowdone[i] = 0;
}

__global__ __launch_bounds__(256) void ln_kernel(const float* __restrict__ hs,
                                                 const float* __restrict__ gamma,
                                                 const float* __restrict__ beta) {
    int n = blockIdx.x;
    int t = threadIdx.x;
    const float4 v = ((const float4*)(hs + (size_t)n * DMODEL))[t];
    float s  = v.x + v.y + v.z + v.w;
    float sq = v.x * v.x + v.y * v.y + v.z * v.z + v.w * v.w;
    __shared__ float red[16];
    for (int o = 16; o > 0; o >>= 1) {
        s  += __shfl_down_sync(0xffffffff, s,  o);
        sq += __shfl_down_sync(0xffffffff, sq, o);
    }
    int wid = t >> 5, lid = t & 31;
    if (lid == 0) { red[wid] = s; red[8 + wid] = sq; }
    __syncthreads();
    if (wid == 0) {
        s  = (lid < 8) ? red[lid]     : 0.f;
        sq = (lid < 8) ? red[8 + lid] : 0.f;
        for (int o = 4; o > 0; o >>= 1) {
            s  += __shfl_down_sync(0xffffffff, s,  o);
            sq += __shfl_down_sync(0xffffffff, sq, o);
        }
        if (lid == 0) { red[0] = s; red[1] = sq; }
    }
    __syncthreads();
    float mean = red[0] * (1.f / DMODEL);
    float var  = red[1] * (1.f / DMODEL) - mean * mean;
    float rstd = rsqrtf(var + LN_EPS);
    const float4 g = ((const float4*)gamma)[t];
    const float4 b = ((const float4*)beta)[t];
    float4 o;
    o.x = (v.x - mean) * rstd * g.x + b.x;
    o.y = (v.y - mean) * rstd * g.y + b.y;
    o.z = (v.z - mean) * rstd * g.z + b.z;
    o.w = (v.w - mean) * rstd * g.w + b.w;
    ushort4 hv = { h_rn(o.x), h_rn(o.y), h_rn(o.z), h_rn(o.w) };
    ((ushort4*)g_xh)[(size_t)n * (DMODEL / 4) + t] = hv;
    size_t a = ((size_t)n * KTOT + 2048) / 4 + t;
    ((ushort4*)g_Ahi)[a] = hv;
}

__global__ void count_kernel(const int* __restrict__ ei, const int* __restrict__ et) {
    int e = blockIdx.x * blockDim.x + threadIdx.x;
    if (e < NEDGE) atomicAdd(&g_cnt[et[e] * N_NODES + ei[NEDGE + e]], 1);
}

__global__ __launch_bounds__(1024) void scan_kernel() {
    int tid = threadIdx.x;
    int lane = tid & 31, wid = tid >> 5;
    int base = tid * 16;
    int loc[16];
    int s = 0;
    #pragma unroll
    for (int i = 0; i < 16; i++) { loc[i] = s; s += g_cnt[base + i]; }
    int inc = s;
    #pragma unroll
    for (int o = 1; o < 32; o <<= 1) {
        int v = __shfl_up_sync(0xffffffff, inc, o);
        if (lane >= o) inc += v;
    }
    __shared__ int wtot[32];
    if (lane == 31) wtot[wid] = inc;
    __syncthreads();
    if (wid == 0) {
        int w = wtot[lane];
        int wi = w;
        #pragma unroll
        for (int o = 1; o < 32; o <<= 1) {
            int v = __shfl_up_sync(0xffffffff, wi, o);
            if (lane >= o) wi += v;
        }
        wtot[lane] = wi - w;
    }
    __syncthreads();
    int ex = wtot[wid] + (inc - s);
    #pragma unroll
    for (int i = 0; i < 16; i++) {
        int o = ex + loc[i];
        g_off[base + i] = o;
        g_cur[base + i] = o;
    }
}

__global__ void bucket_kernel(const int* __restrict__ ei, const int* __restrict__ et) {
    int e = blockIdx.x * blockDim.x + threadIdx.x;
    if (e < NEDGE) {
        int key = et[e] * N_NODES + ei[NEDGE + e];
        int pos = atomicAdd(&g_cur[key], 1);
        g_srcbuf[pos] = ei[e];
    }
}

__global__ __launch_bounds__(128) void gather_kernel() {
    int key = blockIdx.x;
    int node = key & (N_NODES - 1);
    int r = key >> 13;
    int off = g_off[key];
    int cnt = g_cnt[key];
    int t = threadIdx.x;

    float2 acc[4] = { {0.f,0.f}, {0.f,0.f}, {0.f,0.f}, {0.f,0.f} };
    const uint4* xrow = (const uint4*)g_xh;
    int i = 0;
    for (; i + 2 <= cnt; i += 2) {
        int s0 = g_srcbuf[off + i];
        int s1 = g_srcbuf[off + i + 1];
        uint4 v0 = xrow[(size_t)s0 * 128 + t];
        uint4 v1 = xrow[(size_t)s1 * 128 + t];
        const __half2* h0 = (const __half2*)&v0;
        const __half2* h1 = (const __half2*)&v1;
        #pragma unroll
        for (int j = 0; j < 4; j++) {
            float2 f0 = __half22float2(h0[j]);
            float2 f1 = __half22float2(h1[j]);
            acc[j].x += f0.x + f1.x;
            acc[j].y += f0.y + f1.y;
        }
    }
    if (i < cnt) {
        int s0 = g_srcbuf[off + i];
        uint4 v0 = xrow[(size_t)s0 * 128 + t];
        const __half2* h0 = (const __half2*)&v0;
        #pragma unroll
        for (int j = 0; j < 4; j++) {
            float2 f0 = __half22float2(h0[j]);
            acc[j].x += f0.x;
            acc[j].y += f0.y;
        }
    }
    float sc = 1.f / (float)max(cnt, 1);
    ushort4 o0, o1;
    o0.x = h_rn(acc[0].x * sc); o0.y = h_rn(acc[0].y * sc);
    o0.z = h_rn(acc[1].x * sc); o0.w = h_rn(acc[1].y * sc);
    o1.x = h_rn(acc[2].x * sc); o1.y = h_rn(acc[2].y * sc);
    o1.z = h_rn(acc[3].x * sc); o1.w = h_rn(acc[3].y * sc);
    size_t a = ((size_t)node * KTOT + (size_t)r * 1024 + t * 8) >> 2;
    ((ushort4*)g_Ahi)[a] = o0;
    ((ushort4*)g_Ahi)[a + 1] = o1;
}

__global__ void cvt_kernel(const float* __restrict__ src,
                           __half* __restrict__ dst, size_t n4) {
    size_t i = (size_t)blockIdx.x * blockDim.x + threadIdx.x;
    for (; i < n4; i += (size_t)gridDim.x * blockDim.x) {
        float4 v = ((const float4*)src)[i];
        ushort4 hv = { h_rn(v.x), h_rn(v.y), h_rn(v.z), h_rn(v.w) };
        ((ushort4*)dst)[i] = hv;
    }
}

// ---- fused fp16 GEMM1+GEMM2, 1280 blocks, 3-stage cp.async --------------------
#define STAGE_BYTES 49152
#define OFF_BHI 16384
#define NSTAGE 3
#define SMEM_DYN (NSTAGE * STAGE_BYTES)
#define EPIPITCH 264

__device__ __forceinline__ uint32_t a_off(int row, int q) {
    return (uint32_t)(row * 128 + ((q ^ (row & 7)) << 4));
}
__device__ __forceinline__ uint32_t b_off(int row, int q) {
    return (uint32_t)(row * 512 + (((q & 24) | ((q & 7) ^ (row & 7))) << 4));
}

__global__ __launch_bounds__(256, 1) void gemm_fused(
    const __half* __restrict__ A1, const __half* __restrict__ B1,
    const __half* __restrict__ B2,
    __half* __restrict__ mid,
    const float* __restrict__ bias, const float* __restrict__ residual,
    float* __restrict__ outF)
{
    extern __shared__ __align__(1024) char smem[];
    const uint32_t sb = smem_u32(smem);
    const int tid = threadIdx.x, wid = tid >> 5, lane = tid & 31;
    const int b = blockIdx.x;
    const bool isG1 = (b < G1_BLOCKS);

    int rowBase, nBase, K, ldA, ldB;
    const __half* A;
    const __half* B;
    if (isG1) {
        rowBase = (b >> 4) * 128;
        nBase   = (b & 15) * 256;
        K = KTOT; ldA = KTOT; ldB = FINT;
        A = A1; B = B1;
    } else {
        int j = b - G1_BLOCKS;
        rowBase = (j >> 2) * 128;
        nBase   = (j & 3) * 256;
        K = FINT; ldA = FINT; ldB = DMODEL;
        A = mid; B = B2;
        if (tid == 0) {
            while (atomicAdd(&g_rowdone[rowBase >> 7], 0) < 16) { }
        }
        __syncthreads();
        __threadfence();
    }

    const int warp_m = (wid >> 2) * 64;
    const int warp_n = (wid & 3) * 64;
    const int lr = lane & 15, lc = lane >> 4;
    const int nchunk = K >> 6;

    float acc[4][8][4];
    #pragma unroll
    for (int i = 0; i < 4; i++)
        #pragma unroll
        for (int j = 0; j < 8; j++)
            #pragma unroll
            for (int k = 0; k < 4; k++) acc[i][j][k] = 0.f;

    auto load_chunk = [&](int c, int s) {
        const uint32_t sbase = sb + s * STAGE_BYTES;
        const int kb = c * 64;
        #pragma unroll
        for (int i = 0; i < 4; i++) {
            int v = tid + i * 256;
            int row = v >> 3, q = v & 7;
            uint32_t so = sbase + a_off(row, q);
            size_t g = (size_t)(rowBase + row) * ldA + kb + q * 8;
            CP16(so, A + g);
        }
        #pragma unroll
        for (int i = 0; i < 8; i++) {
            int v = tid + i * 256;
            int row = v >> 5, q = v & 31;
            uint32_t so = sbase + OFF_BHI + b_off(row, q);
            size_t g = (size_t)(kb + row) * ldB + nBase + q * 8;
            CP16(so, B + g);
        }
    };

    load_chunk(0, 0); CP_COMMIT();
    load_chunk(1, 1); CP_COMMIT();
    load_chunk(2, 2); CP_COMMIT();

    for (int c = 0; c < nchunk; c++) {
        CP_WAIT2();
        __syncthreads();
        const int slot = c % NSTAGE;
        const uint32_t base = sb + slot * STAGE_BYTES;
        #pragma unroll
        for (int ks = 0; ks < 4; ks++) {
            uint32_t ah[4][4];
            #pragma unroll
            for (int mi = 0; mi < 4; mi++) {
                int row = warp_m + mi * 16 + lr;
                int q = ks * 2 + lc;
                ldsm4(ah[mi], base + a_off(row, q));
            }
            #pragma unroll
            for (int np = 0; np < 4; np++) {
                int row = ks * 16 + lr;
                int q = (warp_n >> 3) + np * 2 + lc;
                uint32_t th[4];
                ldsm4t(th, base + OFF_BHI + b_off(row, q));
                uint32_t b0[2] = { th[0], th[1] }, b1[2] = { th[2], th[3] };
                #pragma unroll
                for (int mi = 0; mi < 4; mi++) {
                    mma16816(acc[mi][np * 2], ah[mi], b0);
                    mma16816(acc[mi][np * 2 + 1], ah[mi], b1);
                }
            }
        }
        __syncthreads();
        if (c + NSTAGE < nchunk) load_chunk(c + NSTAGE, slot);
        CP_COMMIT();
    }

    if (isG1) {
        unsigned short* stH = (unsigned short*)smem;
        #pragma unroll
        for (int mi = 0; mi < 4; mi++) {
            #pragma unroll
            for (int ni = 0; ni < 8; ni++) {
                int rl0 = warp_m + mi * 16 + (lane >> 2);
                int cl  = warp_n + ni * 8 + (lane & 3) * 2;
                #pragma unroll
                for (int h = 0; h < 2; h++) {
                    int rl = rl0 + h * 8;
                    float x0 = acc[mi][ni][h * 2 + 0];
                    float x1 = acc[mi][ni][h * 2 + 1];
                    int gc = nBase + cl;
                    x0 = fmaxf(x0 + bias[gc], 0.f);
                    x1 = fmaxf(x1 + bias[gc + 1], 0.f);
                    ushort2 hv = { h_rn(x0), h_rn(x1) };
                    *(ushort2*)&stH[rl * EPIPITCH + cl] = hv;
                }
            }
        }
        __syncthreads();
        #pragma unroll
        for (int i = 0; i < 16; i++) {
            int idx = tid + i * 256;
            int row = idx >> 5, ch = idx & 31;
            uint4 vh = *(uint4*)&stH[row * EPIPITCH + ch * 8];
            size_t go = (size_t)(rowBase + row) * ldB + nBase + ch * 8;
            *(uint4*)&mid[go] = vh;
        }
        __threadfence();
        __syncthreads();
        if (tid == 0) atomicAdd(&g_rowdone[rowBase >> 7], 1);
    } else {
        #pragma unroll
        for (int mi = 0; mi < 4; mi++) {
            #pragma unroll
            for (int ni = 0; ni < 8; ni++) {
                int r0 = rowBase + warp_m + mi * 16 + (lane >> 2);
                int col = nBase + warp_n + ni * 8 + (lane & 3) * 2;
                #pragma unroll
                for (int h = 0; h < 2; h++) {
                    int row = r0 + h * 8;
                    float x0 = acc[mi][ni][h * 2 + 0];
                    float x1 = acc[mi][ni][h * 2 + 1];
                    size_t go = (size_t)row * ldB + col;
                    float2 res = *(const float2*)&residual[go];
                    float2 y = { x0 + res.x, x1 + res.y };
                    *(float2*)&outF[go] = y;
                }
            }
        }
    }
}

// ---------------- launch -------------------------------------------------------
extern "C" void kernel_launch(void* const* d_in, const int* in_sizes, int n_in,
                              void* d_out, int out_size) {
    const float* hidden = (const float*)d_in[0];
    const float* weight = (const float*)d_in[1];
    const float* root   = (const float*)d_in[2];
    const float* bias   = (const float*)d_in[3];
    const float* wo     = (const float*)d_in[4];
    const float* gamma  = (const float*)d_in[5];
    const float* beta   = (const float*)d_in[6];
    const int*   ei     = (const int*)d_in[7];
    const int*   et     = (const int*)d_in[8];
    float* out = (float*)d_out;

    __half *gAhi, *gBhi, *gWhi, *gMhi;
    cudaGetSymbolAddress((void**)&gAhi, g_Ahi);
    cudaGetSymbolAddress((void**)&gBhi, g_Bhi);
    cudaGetSymbolAddress((void**)&gWhi, g_Whi);
    cudaGetSymbolAddress((void**)&gMhi, g_Mhi);

    cudaFuncSetAttribute(gemm_fused, cudaFuncAttributeMaxDynamicSharedMemorySize, SMEM_DYN);

    static cudaStream_t sA = nullptr;
    static cudaEvent_t evFork = nullptr, evLN = nullptr, evA = nullptr;
    if (!sA) {
        cudaStreamCreateWithFlags(&sA, cudaStreamNonBlocking);
        cudaEventCreateWithFlags(&evFork, cudaEventDisableTiming);
        cudaEventCreateWithFlags(&evLN,   cudaEventDisableTiming);
        cudaEventCreateWithFlags(&evA,    cudaEventDisableTiming);
    }

    cudaEventRecord(evFork, 0);
    cudaStreamWaitEvent(sA, evFork, 0);

    // stream 0: ln first (gather needs it), then weight converts
    ln_kernel<<<N_NODES, 256>>>(hidden, gamma, beta);
    cudaEventRecord(evLN, 0);

    // stream A: zero -> count -> scan -> bucket -> (wait ln) -> gather
    zero_cnt_kernel<<<NKEY / 256, 256, 0, sA>>>();
    count_kernel<<<NEDGE / 256, 256, 0, sA>>>(ei, et);
    scan_kernel<<<1, 1024, 0, sA>>>();
    bucket_kernel<<<NEDGE / 256, 256, 0, sA>>>(ei, et);
    cudaStreamWaitEvent(sA, evLN, 0);
    gather_kernel<<<NKEY, 128, 0, sA>>>();
    cudaEventRecord(evA, sA);

    // stream 0: weight converts overlap the sA chain (incl. gather)
    cvt_kernel<<<2048, 256>>>(weight, gBhi, (size_t)2048 * FINT / 4);
    cvt_kernel<<<1024, 256>>>(root, gBhi + (size_t)2048 * FINT, (size_t)1024 * FINT / 4);
    cvt_kernel<<<1024, 256>>>(wo, gWhi, (size_t)FINT * DMODEL / 4);

    // join: fused GEMM needs gather (sA) + cvts (s0)
    cudaStreamWaitEvent(0, evA, 0);
    gemm_fused<<<G1_BLOCKS + G2_BLOCKS, 256, SMEM_DYN>>>(
        gAhi, gBhi, gWhi, gMhi, bias, hidden, out);
}

// round 16
// speedup vs baseline: 1.0428x; 1.0161x over previous
#include <cuda_runtime.h>
#include <cuda_fp16.h>
#include <cstdint>
#include <math.h>

#define N_NODES 8192
#define DMODEL 1024
#define FINT 4096
#define KTOT 3072
#define NEDGE 262144
#define NKEY (2 * N_NODES)
#define LN_EPS 1e-6f
#define NROWBLK 64
#define G1_BLOCKS 1024
#define G2_BLOCKS 256

// ---------------- PTX helpers ---------------------------------------------------
__device__ __forceinline__ uint32_t smem_u32(const void* p) {
    uint32_t a;
    asm("{ .reg .u64 t; cvta.to.shared.u64 t, %1; cvt.u32.u64 %0, t; }" : "=r"(a) : "l"(p));
    return a;
}
#define CP16(dst, src) asm volatile("cp.async.cg.shared.global [%0], [%1], 16;" :: "r"(dst), "l"(src))
#define CP_COMMIT()    asm volatile("cp.async.commit_group;" ::: "memory")
#define CP_WAIT2()     asm volatile("cp.async.wait_group 2;" ::: "memory")

__device__ __forceinline__ void ldsm4(uint32_t* r, uint32_t a) {
    asm volatile("ldmatrix.sync.aligned.m8n8.x4.shared.b16 {%0,%1,%2,%3}, [%4];"
                 : "=r"(r[0]), "=r"(r[1]), "=r"(r[2]), "=r"(r[3]) : "r"(a));
}
__device__ __forceinline__ void ldsm4t(uint32_t* r, uint32_t a) {
    asm volatile("ldmatrix.sync.aligned.m8n8.x4.trans.shared.b16 {%0,%1,%2,%3}, [%4];"
                 : "=r"(r[0]), "=r"(r[1]), "=r"(r[2]), "=r"(r[3]) : "r"(a));
}
__device__ __forceinline__ void mma16816(float* d, const uint32_t* a, const uint32_t* b) {
    asm volatile("mma.sync.aligned.m16n8k16.row.col.f32.f16.f16.f32 "
                 "{%0,%1,%2,%3}, {%4,%5,%6,%7}, {%8,%9}, {%0,%1,%2,%3};"
                 : "+f"(d[0]), "+f"(d[1]), "+f"(d[2]), "+f"(d[3])
                 : "r"(a[0]), "r"(a[1]), "r"(a[2]), "r"(a[3]), "r"(b[0]), "r"(b[1]));
}

// ---------------- scratch ----------------------------------------------------
__device__ __half g_xh[(size_t)N_NODES * DMODEL];
__device__ __half g_Ahi[(size_t)N_NODES * KTOT];
__device__ __half g_Bhi[(size_t)KTOT * FINT];
__device__ __half g_Whi[(size_t)FINT * DMODEL];
__device__ __half g_Mhi[(size_t)N_NODES * FINT];
__device__ __align__(16) int g_cnt[NKEY];
__device__ __align__(16) int g_off[NKEY];
__device__ __align__(16) int g_cur[NKEY];
__device__ int g_srcbuf[NEDGE];
__device__ int g_rowdone[NROWBLK];

__device__ __forceinline__ unsigned short h_rn(float x) {
    __half h = __float2half_rn(x);
    return *(unsigned short*)&h;
}

// ---------------- pipeline kernels ---------------------------------------------
__global__ void zero_cnt_kernel() {
    int i = blockIdx.x * blockDim.x + threadIdx.x;
    if (i < NKEY) g_cnt[i] = 0;
    if (i < NROWBLK) g_rowdone[i] = 0;
}

__global__ __launch_bounds__(256) void ln_kernel(const float* __restrict__ hs,
                                                 const float* __restrict__ gamma,
                                                 const float* __restrict__ beta) {
    int n = blockIdx.x;
    int t = threadIdx.x;
    const float4 v = ((const float4*)(hs + (size_t)n * DMODEL))[t];
    float s  = v.x + v.y + v.z + v.w;
    float sq = v.x * v.x + v.y * v.y + v.z * v.z + v.w * v.w;
    __shared__ float red[16];
    for (int o = 16; o > 0; o >>= 1) {
        s  += __shfl_down_sync(0xffffffff, s,  o);
        sq += __shfl_down_sync(0xffffffff, sq, o);
    }
    int wid = t >> 5, lid = t & 31;
    if (lid == 0) { red[wid] = s; red[8 + wid] = sq; }
    __syncthreads();
    if (wid == 0) {
        s  = (lid < 8) ? red[lid]     : 0.f;
        sq = (lid < 8) ? red[8 + lid] : 0.f;
        for (int o = 4; o > 0; o >>= 1) {
            s  += __shfl_down_sync(0xffffffff, s,  o);
            sq += __shfl_down_sync(0xffffffff, sq, o);
        }
        if (lid == 0) { red[0] = s; red[1] = sq; }
    }
    __syncthreads();
    float mean = red[0] * (1.f / DMODEL);
    float var  = red[1] * (1.f / DMODEL) - mean * mean;
    float rstd = rsqrtf(var + LN_EPS);
    const float4 g = ((const float4*)gamma)[t];
    const float4 b = ((const float4*)beta)[t];
    float4 o;
    o.x = (v.x - mean) * rstd * g.x + b.x;
    o.y = (v.y - mean) * rstd * g.y + b.y;
    o.z = (v.z - mean) * rstd * g.z + b.z;
    o.w = (v.w - mean) * rstd * g.w + b.w;
    ushort4 hv = { h_rn(o.x), h_rn(o.y), h_rn(o.z), h_rn(o.w) };
    ((ushort4*)g_xh)[(size_t)n * (DMODEL / 4) + t] = hv;
    size_t a = ((size_t)n * KTOT + 2048) / 4 + t;
    ((ushort4*)g_Ahi)[a] = hv;
}

__global__ void count_kernel(const int* __restrict__ ei, const int* __restrict__ et) {
    int e = blockIdx.x * blockDim.x + threadIdx.x;
    if (e < NEDGE) atomicAdd(&g_cnt[et[e] * N_NODES + ei[NEDGE + e]], 1);
}

// two-level shfl scan over 16384 counts (1024 threads x 16), int4-vectorized I/O
__global__ __launch_bounds__(1024) void scan_kernel() {
    int tid = threadIdx.x;
    int lane = tid & 31, wid = tid >> 5;
    int base = tid * 16;

    int4 c[4];
    const int4* cp = (const int4*)&g_cnt[base];
    #pragma unroll
    for (int i = 0; i < 4; i++) c[i] = cp[i];

    int loc[16];
    int s = 0;
    #pragma unroll
    for (int i = 0; i < 4; i++) {
        loc[i * 4 + 0] = s; s += ((int*)&c[i])[0];
        loc[i * 4 + 1] = s; s += ((int*)&c[i])[1];
        loc[i * 4 + 2] = s; s += ((int*)&c[i])[2];
        loc[i * 4 + 3] = s; s += ((int*)&c[i])[3];
    }

    int inc = s;
    #pragma unroll
    for (int o = 1; o < 32; o <<= 1) {
        int v = __shfl_up_sync(0xffffffff, inc, o);
        if (lane >= o) inc += v;
    }
    __shared__ int wtot[32];
    if (lane == 31) wtot[wid] = inc;
    __syncthreads();
    if (wid == 0) {
        int w = wtot[lane];
        int wi = w;
        #pragma unroll
        for (int o = 1; o < 32; o <<= 1) {
            int v = __shfl_up_sync(0xffffffff, wi, o);
            if (lane >= o) wi += v;
        }
        wtot[lane] = wi - w;
    }
    __syncthreads();
    int ex = wtot[wid] + (inc - s);

    int4* op = (int4*)&g_off[base];
    int4* up = (int4*)&g_cur[base];
    #pragma unroll
    for (int i = 0; i < 4; i++) {
        int4 o4;
        o4.x = ex + loc[i * 4 + 0];
        o4.y = ex + loc[i * 4 + 1];
        o4.z = ex + loc[i * 4 + 2];
        o4.w = ex + loc[i * 4 + 3];
        op[i] = o4;
        up[i] = o4;
    }
}

__global__ void bucket_kernel(const int* __restrict__ ei, const int* __restrict__ et) {
    int e = blockIdx.x * blockDim.x + threadIdx.x;
    if (e < NEDGE) {
        int key = et[e] * N_NODES + ei[NEDGE + e];
        int pos = atomicAdd(&g_cur[key], 1);
        g_srcbuf[pos] = ei[e];
    }
}

__global__ __launch_bounds__(128) void gather_kernel() {
    int key = blockIdx.x;
    int node = key & (N_NODES - 1);
    int r = key >> 13;
    int off = g_off[key];
    int cnt = g_cnt[key];
    int t = threadIdx.x;

    float2 acc[4] = { {0.f,0.f}, {0.f,0.f}, {0.f,0.f}, {0.f,0.f} };
    const uint4* xrow = (const uint4*)g_xh;
    int i = 0;
    for (; i + 2 <= cnt; i += 2) {
        int s0 = g_srcbuf[off + i];
        int s1 = g_srcbuf[off + i + 1];
        uint4 v0 = xrow[(size_t)s0 * 128 + t];
        uint4 v1 = xrow[(size_t)s1 * 128 + t];
        const __half2* h0 = (const __half2*)&v0;
        const __half2* h1 = (const __half2*)&v1;
        #pragma unroll
        for (int j = 0; j < 4; j++) {
            float2 f0 = __half22float2(h0[j]);
            float2 f1 = __half22float2(h1[j]);
            acc[j].x += f0.x + f1.x;
            acc[j].y += f0.y + f1.y;
        }
    }
    if (i < cnt) {
        int s0 = g_srcbuf[off + i];
        uint4 v0 = xrow[(size_t)s0 * 128 + t];
        const __half2* h0 = (const __half2*)&v0;
        #pragma unroll
        for (int j = 0; j < 4; j++) {
            float2 f0 = __half22float2(h0[j]);
            acc[j].x += f0.x;
            acc[j].y += f0.y;
        }
    }
    float sc = 1.f / (float)max(cnt, 1);
    ushort4 o0, o1;
    o0.x = h_rn(acc[0].x * sc); o0.y = h_rn(acc[0].y * sc);
    o0.z = h_rn(acc[1].x * sc); o0.w = h_rn(acc[1].y * sc);
    o1.x = h_rn(acc[2].x * sc); o1.y = h_rn(acc[2].y * sc);
    o1.z = h_rn(acc[3].x * sc); o1.w = h_rn(acc[3].y * sc);
    size_t a = ((size_t)node * KTOT + (size_t)r * 1024 + t * 8) >> 2;
    ((ushort4*)g_Ahi)[a] = o0;
    ((ushort4*)g_Ahi)[a + 1] = o1;
}

__global__ void cvt_kernel(const float* __restrict__ src,
                           __half* __restrict__ dst, size_t n4) {
    size_t i = (size_t)blockIdx.x * blockDim.x + threadIdx.x;
    for (; i < n4; i += (size_t)gridDim.x * blockDim.x) {
        float4 v = ((const float4*)src)[i];
        ushort4 hv = { h_rn(v.x), h_rn(v.y), h_rn(v.z), h_rn(v.w) };
        ((ushort4*)dst)[i] = hv;
    }
}

// ---- fused fp16 GEMM1+GEMM2, 1280 blocks, 3-stage cp.async --------------------
#define STAGE_BYTES 49152
#define OFF_BHI 16384
#define NSTAGE 3
#define SMEM_DYN (NSTAGE * STAGE_BYTES)
#define EPIPITCH 264

__device__ __forceinline__ uint32_t a_off(int row, int q) {
    return (uint32_t)(row * 128 + ((q ^ (row & 7)) << 4));
}
__device__ __forceinline__ uint32_t b_off(int row, int q) {
    return (uint32_t)(row * 512 + (((q & 24) | ((q & 7) ^ (row & 7))) << 4));
}

__global__ __launch_bounds__(256, 1) void gemm_fused(
    const __half* __restrict__ A1, const __half* __restrict__ B1,
    const __half* __restrict__ B2,
    __half* __restrict__ mid,
    const float* __restrict__ bias, const float* __restrict__ residual,
    float* __restrict__ outF)
{
    extern __shared__ __align__(1024) char smem[];
    const uint32_t sb = smem_u32(smem);
    const int tid = threadIdx.x, wid = tid >> 5, lane = tid & 31;
    const int b = blockIdx.x;
    const bool isG1 = (b < G1_BLOCKS);

    int rowBase, nBase, K, ldA, ldB;
    const __half* A;
    const __half* B;
    if (isG1) {
        rowBase = (b >> 4) * 128;
        nBase   = (b & 15) * 256;
        K = KTOT; ldA = KTOT; ldB = FINT;
        A = A1; B = B1;
    } else {
        int j = b - G1_BLOCKS;
        rowBase = (j >> 2) * 128;
        nBase   = (j & 3) * 256;
        K = FINT; ldA = FINT; ldB = DMODEL;
        A = mid; B = B2;
        if (tid == 0) {
            while (atomicAdd(&g_rowdone[rowBase >> 7], 0) < 16) { }
        }
        __syncthreads();
        __threadfence();
    }

    const int warp_m = (wid >> 2) * 64;
    const int warp_n = (wid & 3) * 64;
    const int lr = lane & 15, lc = lane >> 4;
    const int nchunk = K >> 6;

    float acc[4][8][4];
    #pragma unroll
    for (int i = 0; i < 4; i++)
        #pragma unroll
        for (int j = 0; j < 8; j++)
            #pragma unroll
            for (int k = 0; k < 4; k++) acc[i][j][k] = 0.f;

    auto load_chunk = [&](int c, int s) {
        const uint32_t sbase = sb + s * STAGE_BYTES;
        const int kb = c * 64;
        #pragma unroll
        for (int i = 0; i < 4; i++) {
            int v = tid + i * 256;
            int row = v >> 3, q = v & 7;
            uint32_t so = sbase + a_off(row, q);
            size_t g = (size_t)(rowBase + row) * ldA + kb + q * 8;
            CP16(so, A + g);
        }
        #pragma unroll
        for (int i = 0; i < 8; i++) {
            int v = tid + i * 256;
            int row = v >> 5, q = v & 31;
            uint32_t so = sbase + OFF_BHI + b_off(row, q);
            size_t g = (size_t)(kb + row) * ldB + nBase + q * 8;
            CP16(so, B + g);
        }
    };

    load_chunk(0, 0); CP_COMMIT();
    load_chunk(1, 1); CP_COMMIT();
    load_chunk(2, 2); CP_COMMIT();

    for (int c = 0; c < nchunk; c++) {
        CP_WAIT2();
        __syncthreads();
        const int slot = c % NSTAGE;
        const uint32_t base = sb + slot * STAGE_BYTES;
        #pragma unroll
        for (int ks = 0; ks < 4; ks++) {
            uint32_t ah[4][4];
            #pragma unroll
            for (int mi = 0; mi < 4; mi++) {
                int row = warp_m + mi * 16 + lr;
                int q = ks * 2 + lc;
                ldsm4(ah[mi], base + a_off(row, q));
            }
            #pragma unroll
            for (int np = 0; np < 4; np++) {
                int row = ks * 16 + lr;
                int q = (warp_n >> 3) + np * 2 + lc;
                uint32_t th[4];
                ldsm4t(th, base + OFF_BHI + b_off(row, q));
                uint32_t b0[2] = { th[0], th[1] }, b1[2] = { th[2], th[3] };
                #pragma unroll
                for (int mi = 0; mi < 4; mi++) {
                    mma16816(acc[mi][np * 2], ah[mi], b0);
                    mma16816(acc[mi][np * 2 + 1], ah[mi], b1);
                }
            }
        }
        __syncthreads();
        if (c + NSTAGE < nchunk) load_chunk(c + NSTAGE, slot);
        CP_COMMIT();
    }

    if (isG1) {
        unsigned short* stH = (unsigned short*)smem;
        #pragma unroll
        for (int mi = 0; mi < 4; mi++) {
            #pragma unroll
            for (int ni = 0; ni < 8; ni++) {
                int rl0 = warp_m + mi * 16 + (lane >> 2);
                int cl  = warp_n + ni * 8 + (lane & 3) * 2;
                #pragma unroll
                for (int h = 0; h < 2; h++) {
                    int rl = rl0 + h * 8;
                    float x0 = acc[mi][ni][h * 2 + 0];
                    float x1 = acc[mi][ni][h * 2 + 1];
                    int gc = nBase + cl;
                    x0 = fmaxf(x0 + bias[gc], 0.f);
                    x1 = fmaxf(x1 + bias[gc + 1], 0.f);
                    ushort2 hv = { h_rn(x0), h_rn(x1) };
                    *(ushort2*)&stH[rl * EPIPITCH + cl] = hv;
                }
            }
        }
        __syncthreads();
        #pragma unroll
        for (int i = 0; i < 16; i++) {
            int idx = tid + i * 256;
            int row = idx >> 5, ch = idx & 31;
            uint4 vh = *(uint4*)&stH[row * EPIPITCH + ch * 8];
            size_t go = (size_t)(rowBase + row) * ldB + nBase + ch * 8;
            *(uint4*)&mid[go] = vh;
        }
        __threadfence();
        __syncthreads();
        if (tid == 0) atomicAdd(&g_rowdone[rowBase >> 7], 1);
    } else {
        #pragma unroll
        for (int mi = 0; mi < 4; mi++) {
            #pragma unroll
            for (int ni = 0; ni < 8; ni++) {
                int r0 = rowBase + warp_m + mi * 16 + (lane >> 2);
                int col = nBase + warp_n + ni * 8 + (lane & 3) * 2;
                #pragma unroll
                for (int h = 0; h < 2; h++) {
                    int row = r0 + h * 8;
                    float x0 = acc[mi][ni][h * 2 + 0];
                    float x1 = acc[mi][ni][h * 2 + 1];
                    size_t go = (size_t)row * ldB + col;
                    float2 res = *(const float2*)&residual[go];
                    float2 y = { x0 + res.x, x1 + res.y };
                    *(float2*)&outF[go] = y;
                }
            }
        }
    }
}

// ---------------- launch -------------------------------------------------------
extern "C" void kernel_launch(void* const* d_in, const int* in_sizes, int n_in,
                              void* d_out, int out_size) {
    const float* hidden = (const float*)d_in[0];
    const float* weight = (const float*)d_in[1];
    const float* root   = (const float*)d_in[2];
    const float* bias   = (const float*)d_in[3];
    const float* wo     = (const float*)d_in[4];
    const float* gamma  = (const float*)d_in[5];
    const float* beta   = (const float*)d_in[6];
    const int*   ei     = (const int*)d_in[7];
    const int*   et     = (const int*)d_in[8];
    float* out = (float*)d_out;

    __half *gAhi, *gBhi, *gWhi, *gMhi;
    cudaGetSymbolAddress((void**)&gAhi, g_Ahi);
    cudaGetSymbolAddress((void**)&gBhi, g_Bhi);
    cudaGetSymbolAddress((void**)&gWhi, g_Whi);
    cudaGetSymbolAddress((void**)&gMhi, g_Mhi);

    cudaFuncSetAttribute(gemm_fused, cudaFuncAttributeMaxDynamicSharedMemorySize, SMEM_DYN);

    static cudaStream_t sA = nullptr;
    static cudaEvent_t evFork = nullptr, evLN = nullptr, evA = nullptr;
    if (!sA) {
        cudaStreamCreateWithFlags(&sA, cudaStreamNonBlocking);
        cudaEventCreateWithFlags(&evFork, cudaEventDisableTiming);
        cudaEventCreateWithFlags(&evLN,   cudaEventDisableTiming);
        cudaEventCreateWithFlags(&evA,    cudaEventDisableTiming);
    }

    cudaEventRecord(evFork, 0);
    cudaStreamWaitEvent(sA, evFork, 0);

    // stream 0: ln first (gather needs it), then weight converts
    ln_kernel<<<N_NODES, 256>>>(hidden, gamma, beta);
    cudaEventRecord(evLN, 0);

    // stream A: zero -> count -> scan -> bucket -> (wait ln) -> gather
    zero_cnt_kernel<<<NKEY / 256, 256, 0, sA>>>();
    count_kernel<<<NEDGE / 256, 256, 0, sA>>>(ei, et);
    scan_kernel<<<1, 1024, 0, sA>>>();
    bucket_kernel<<<NEDGE / 256, 256, 0, sA>>>(ei, et);
    cudaStreamWaitEvent(sA, evLN, 0);
    gather_kernel<<<NKEY, 128, 0, sA>>>();
    cudaEventRecord(evA, sA);

    // stream 0: weight converts overlap the sA chain (incl. gather)
    cvt_kernel<<<2048, 256>>>(weight, gBhi, (size_t)2048 * FINT / 4);
    cvt_kernel<<<1024, 256>>>(root, gBhi + (size_t)2048 * FINT, (size_t)1024 * FINT / 4);
    cvt_kernel<<<1024, 256>>>(wo, gWhi, (size_t)FINT * DMODEL / 4);

    // join: fused GEMM needs gather (sA) + cvts (s0)
    cudaStreamWaitEvent(0, evA, 0);
    gemm_fused<<<G1_BLOCKS + G2_BLOCKS, 256, SMEM_DYN>>>(
        gAhi, gBhi, gWhi, gMhi, bias, hidden, out);
}